// round 1
// baseline (speedup 1.0000x reference)
#include <cuda_runtime.h>

#define cB 2
#define cN 2048
#define cDIM 1024
#define cH 16
#define cD 64
#define cE 3072      // 3*DIM
#define cM 4096      // B*N
#define cK 1024

// Scratch: q,k,v in [B,H,N,D] layout (16 MB each)
__device__ float g_q[cB * cH * cN * cD];
__device__ float g_k[cB * cH * cN * cD];
__device__ float g_v[cB * cH * cN * cD];

// ---------------------------------------------------------------------------
// Kernel 1: qkv = x @ W^T + b, scattered into g_q/g_k/g_v as [B,H,N,D]
// C[m][e] = sum_k x[m][k] * w[e][k];  e = h*192 + d*3 + j  (j: 0=q,1=k,2=v)
// Tiling: BM=BN=128, BK=16, 256 threads, 8x8 per thread (split mapping).
// ---------------------------------------------------------------------------
__global__ __launch_bounds__(256) void qkv_gemm(const float* __restrict__ x,
                                                const float* __restrict__ w,
                                                const float* __restrict__ bias) {
    __shared__ float As[16][128];
    __shared__ float Bs[16][128];
    const int tid = threadIdx.x;
    const int tx = tid & 15;
    const int ty = tid >> 4;
    const int m0 = blockIdx.y * 128;
    const int e0 = blockIdx.x * 128;

    float acc[8][8];
#pragma unroll
    for (int i = 0; i < 8; i++)
#pragma unroll
        for (int j = 0; j < 8; j++) acc[i][j] = 0.f;

    for (int kt = 0; kt < cK; kt += 16) {
#pragma unroll
        for (int p = 0; p < 2; p++) {
            int id  = tid + p * 256;
            int row = id >> 2;          // 0..127
            int q4  = (id & 3) * 4;     // 0,4,8,12
            float4 av = *(const float4*)(x + (size_t)(m0 + row) * cK + kt + q4);
            As[q4 + 0][row] = av.x;
            As[q4 + 1][row] = av.y;
            As[q4 + 2][row] = av.z;
            As[q4 + 3][row] = av.w;
            float4 bv = *(const float4*)(w + (size_t)(e0 + row) * cK + kt + q4);
            Bs[q4 + 0][row] = bv.x;
            Bs[q4 + 1][row] = bv.y;
            Bs[q4 + 2][row] = bv.z;
            Bs[q4 + 3][row] = bv.w;
        }
        __syncthreads();
#pragma unroll
        for (int k = 0; k < 16; k++) {
            float a[8], b[8];
            *(float4*)&a[0] = *(const float4*)&As[k][ty * 4];
            *(float4*)&a[4] = *(const float4*)&As[k][64 + ty * 4];
            *(float4*)&b[0] = *(const float4*)&Bs[k][tx * 4];
            *(float4*)&b[4] = *(const float4*)&Bs[k][64 + tx * 4];
#pragma unroll
            for (int i = 0; i < 8; i++)
#pragma unroll
                for (int j = 0; j < 8; j++)
                    acc[i][j] += a[i] * b[j];
        }
        __syncthreads();
    }

    // Epilogue: add bias, scatter into q/k/v [B,H,N,D]
#pragma unroll
    for (int i = 0; i < 8; i++) {
        int m  = m0 + ((i < 4) ? (ty * 4 + i) : (64 + ty * 4 + i - 4));
        int bb = m >> 11;          // m / N
        int n  = m & (cN - 1);
#pragma unroll
        for (int j = 0; j < 8; j++) {
            int e = e0 + ((j < 4) ? (tx * 4 + j) : (64 + tx * 4 + j - 4));
            float v = acc[i][j] + __ldg(bias + e);
            int h   = e / 192;
            int rem = e - h * 192;
            int d   = rem / 3;
            int jj  = rem - d * 3;
            size_t idx = ((size_t)(bb * cH + h) * cN + n) * cD + d;
            if (jj == 0)      g_q[idx] = v;
            else if (jj == 1) g_k[idx] = v;
            else              g_v[idx] = v;
        }
    }
}

// ---------------------------------------------------------------------------
// Kernel 2: in-place RMS-norm over head dim for q (blockIdx.y=0) and k (=1).
// One warp per row of 64: each lane owns 2 elems, shfl-reduce the sum-sq.
// ---------------------------------------------------------------------------
__global__ __launch_bounds__(256) void rmsnorm(const float* __restrict__ qw,
                                               const float* __restrict__ kw) {
    int warp = threadIdx.x >> 5;
    int lane = threadIdx.x & 31;
    size_t row = (size_t)blockIdx.x * 8 + warp;     // < B*H*N = 65536
    float* base = blockIdx.y ? g_k : g_q;
    const float* wv = blockIdx.y ? kw : qw;

    float2 v = *(float2*)(base + row * cD + lane * 2);
    float ss = v.x * v.x + v.y * v.y;
#pragma unroll
    for (int o = 16; o > 0; o >>= 1) ss += __shfl_xor_sync(0xffffffffu, ss, o);
    float inv = rsqrtf(ss * (1.0f / cD) + 1e-6f);
    float2 g = *(const float2*)(wv + lane * 2);
    v.x *= inv * g.x;
    v.y *= inv * g.y;
    *(float2*)(base + row * cD + lane * 2) = v;
}

// ---------------------------------------------------------------------------
// Kernel 3: attention, flash-style 64x64 tiles WITHOUT online max:
// after RMS norm, |q|=|k|=8 so |score| <= 8 -> exp(s) is always safe in fp32.
// Accumulate o += exp(s)*v and per-row l += exp(s); divide once at the end.
// Smem: Qs row-major, K staged TRANSPOSED ([d][c]) -> conflict-free LDS.128.
// 256 threads, 4x4 per thread. Static smem = 48 KB exactly.
// ---------------------------------------------------------------------------
__global__ __launch_bounds__(256) void attn(float* __restrict__ out) {
    __shared__ float Qs[64][64];
    __shared__ float KV[64][64];   // K as [d][c] in S phase, V as [c][d] in PV phase
    __shared__ float Ps[64][64];
    const int tid = threadIdx.x;
    const int tx = tid & 15;
    const int ty = tid >> 4;
    const int bh = blockIdx.y;             // 0..31  (b*H + h)
    const int q0 = blockIdx.x * 64;
    const float* qb = g_q + (size_t)bh * cN * cD;
    const float* kb = g_k + (size_t)bh * cN * cD;
    const float* vb = g_v + (size_t)bh * cN * cD;

    // Load Q tile (coalesced, row-major)
#pragma unroll
    for (int p = 0; p < 4; p++) {
        int l  = tid + p * 256;
        int r  = l >> 4;
        int c4 = (l & 15) * 4;
        *(float4*)&Qs[r][c4] = *(const float4*)(qb + (size_t)(q0 + r) * cD + c4);
    }

    float o[4][4];
    float lsum[4];
#pragma unroll
    for (int i = 0; i < 4; i++) {
        lsum[i] = 0.f;
#pragma unroll
        for (int j = 0; j < 4; j++) o[i][j] = 0.f;
    }

    for (int kt = 0; kt < cN; kt += 64) {
        __syncthreads();   // prior-iter V reads done (also covers Q load on iter 0)
        // Load K tile transposed: KV[d][c] = k[kt+c][d]
#pragma unroll
        for (int p = 0; p < 4; p++) {
            int l  = tid + p * 256;
            int c  = l & 63;
            int d4 = (l >> 6) * 4;
            float4 t = *(const float4*)(kb + (size_t)(kt + c) * cD + d4);
            KV[d4 + 0][c] = t.x;
            KV[d4 + 1][c] = t.y;
            KV[d4 + 2][c] = t.z;
            KV[d4 + 3][c] = t.w;
        }
        __syncthreads();

        // S = Q K^T for this tile
        float s[4][4];
#pragma unroll
        for (int i = 0; i < 4; i++)
#pragma unroll
            for (int j = 0; j < 4; j++) s[i][j] = 0.f;

#pragma unroll
        for (int d4 = 0; d4 < 64; d4 += 4) {
            float qf[4][4], kf[4][4];
#pragma unroll
            for (int i = 0; i < 4; i++) {
                float4 t = *(const float4*)&Qs[ty * 4 + i][d4];
                qf[i][0] = t.x; qf[i][1] = t.y; qf[i][2] = t.z; qf[i][3] = t.w;
            }
#pragma unroll
            for (int dd = 0; dd < 4; dd++) {
                float4 t = *(const float4*)&KV[d4 + dd][tx * 4];
                kf[dd][0] = t.x; kf[dd][1] = t.y; kf[dd][2] = t.z; kf[dd][3] = t.w;
            }
#pragma unroll
            for (int i = 0; i < 4; i++)
#pragma unroll
                for (int j = 0; j < 4; j++)
#pragma unroll
                    for (int dd = 0; dd < 4; dd++)
                        s[i][j] += qf[i][dd] * kf[dd][j];
        }

        // P = exp(S * scale); accumulate row sums; stage P in smem
#pragma unroll
        for (int i = 0; i < 4; i++) {
            float4 pv;
            pv.x = __expf(s[i][0] * 0.125f);
            pv.y = __expf(s[i][1] * 0.125f);
            pv.z = __expf(s[i][2] * 0.125f);
            pv.w = __expf(s[i][3] * 0.125f);
            lsum[i] += pv.x + pv.y + pv.z + pv.w;
            *(float4*)&Ps[ty * 4 + i][tx * 4] = pv;
        }
        __syncthreads();   // everyone done reading K; P visible

        // Load V tile row-major into the same buffer
#pragma unroll
        for (int p = 0; p < 4; p++) {
            int l  = tid + p * 256;
            int r  = l >> 4;
            int c4 = (l & 15) * 4;
            *(float4*)&KV[r][c4] = *(const float4*)(vb + (size_t)(kt + r) * cD + c4);
        }
        __syncthreads();

        // O += P * V
#pragma unroll
        for (int c4 = 0; c4 < 64; c4 += 4) {
            float pf[4][4], vf[4][4];
#pragma unroll
            for (int i = 0; i < 4; i++) {
                float4 t = *(const float4*)&Ps[ty * 4 + i][c4];
                pf[i][0] = t.x; pf[i][1] = t.y; pf[i][2] = t.z; pf[i][3] = t.w;
            }
#pragma unroll
            for (int cc = 0; cc < 4; cc++) {
                float4 t = *(const float4*)&KV[c4 + cc][tx * 4];
                vf[cc][0] = t.x; vf[cc][1] = t.y; vf[cc][2] = t.z; vf[cc][3] = t.w;
            }
#pragma unroll
            for (int i = 0; i < 4; i++)
#pragma unroll
                for (int j = 0; j < 4; j++)
#pragma unroll
                    for (int cc = 0; cc < 4; cc++)
                        o[i][j] += pf[i][cc] * vf[cc][j];
        }
    }

    // Reduce row sums across the 16 tx lanes (each holds its 4 cols' partials)
#pragma unroll
    for (int i = 0; i < 4; i++) {
#pragma unroll
        for (int off = 1; off < 16; off <<= 1)
            lsum[i] += __shfl_xor_sync(0xffffffffu, lsum[i], off);
    }

    // Write out: out[b][n][h*64 + d]
    int bb = bh >> 4;
    int h  = bh & 15;
#pragma unroll
    for (int i = 0; i < 4; i++) {
        int n = q0 + ty * 4 + i;
        float inv = 1.0f / lsum[i];
        float4 r4;
        r4.x = o[i][0] * inv;
        r4.y = o[i][1] * inv;
        r4.z = o[i][2] * inv;
        r4.w = o[i][3] * inv;
        *(float4*)(out + ((size_t)(bb * cN + n)) * cDIM + h * cD + tx * 4) = r4;
    }
}

// ---------------------------------------------------------------------------
extern "C" void kernel_launch(void* const* d_in, const int* in_sizes, int n_in,
                              void* d_out, int out_size) {
    const float* x        = (const float*)d_in[0];
    const float* qkv_w    = (const float*)d_in[1];
    const float* qkv_b    = (const float*)d_in[2];
    const float* q_norm_w = (const float*)d_in[3];
    const float* k_norm_w = (const float*)d_in[4];
    float* out = (float*)d_out;

    dim3 g1(cE / 128, cM / 128);         // 24 x 32
    qkv_gemm<<<g1, 256>>>(x, qkv_w, qkv_b);

    dim3 g2((cB * cH * cN) / 8, 2);      // 8192 x 2
    rmsnorm<<<g2, 256>>>(q_norm_w, k_norm_w);

    dim3 g3(cN / 64, cB * cH);           // 32 x 32
    attn<<<g3, 256>>>(out);
}

// round 4
// speedup vs baseline: 1.0410x; 1.0410x over previous
#include <cuda_runtime.h>

#define cB 2
#define cN 2048
#define cDIM 1024
#define cH 16
#define cD 64
#define cE 3072      // 3*DIM
#define cM 4096      // B*N
#define cK 1024

// Scratch: q,k,v in [B,H,N,D] layout (16 MB each)
__device__ float g_q[cB * cH * cN * cD];
__device__ float g_k[cB * cH * cN * cD];
__device__ float g_v[cB * cH * cN * cD];

// ---------------------------------------------------------------------------
// Kernel 1: qkv = x @ W^T + b, scattered into g_q/g_k/g_v as [B,H,N,D].
// 128x128 tile, BK=16, 256 threads, 8x8/thread, DOUBLE-BUFFERED smem with
// register prefetch: one __syncthreads per K-iteration, LDG latency overlapped
// with the 1024-FMA compute block.
// ---------------------------------------------------------------------------
__global__ __launch_bounds__(256) void qkv_gemm(const float* __restrict__ x,
                                                const float* __restrict__ w,
                                                const float* __restrict__ bias) {
    __shared__ float As[2][16][128];
    __shared__ float Bs[2][16][128];
    const int tid = threadIdx.x;
    const int tx = tid & 15;
    const int ty = tid >> 4;
    const int m0 = blockIdx.y * 128;
    const int e0 = blockIdx.x * 128;

    // Fixed per-thread gmem coordinates for the two load chunks
    const int row0 = tid >> 2;                // 0..63
    const int c0   = (tid & 3) * 4;
    const int row1 = (tid + 256) >> 2;        // 64..127
    const int c1   = ((tid + 256) & 3) * 4;

    const float* xa0 = x + (size_t)(m0 + row0) * cK + c0;
    const float* xa1 = x + (size_t)(m0 + row1) * cK + c1;
    const float* wb0 = w + (size_t)(e0 + row0) * cK + c0;
    const float* wb1 = w + (size_t)(e0 + row1) * cK + c1;

    float acc[8][8];
#pragma unroll
    for (int i = 0; i < 8; i++)
#pragma unroll
        for (int j = 0; j < 8; j++) acc[i][j] = 0.f;

    // Prefetch tile 0
    float4 pa0 = *(const float4*)(xa0);
    float4 pa1 = *(const float4*)(xa1);
    float4 pb0 = *(const float4*)(wb0);
    float4 pb1 = *(const float4*)(wb1);

    int buf = 0;
    for (int kt = 0; kt < 64; kt++) {
        // Store prefetched tile (transposed) into current buffer
        As[buf][c0 + 0][row0] = pa0.x;
        As[buf][c0 + 1][row0] = pa0.y;
        As[buf][c0 + 2][row0] = pa0.z;
        As[buf][c0 + 3][row0] = pa0.w;
        As[buf][c1 + 0][row1] = pa1.x;
        As[buf][c1 + 1][row1] = pa1.y;
        As[buf][c1 + 2][row1] = pa1.z;
        As[buf][c1 + 3][row1] = pa1.w;
        Bs[buf][c0 + 0][row0] = pb0.x;
        Bs[buf][c0 + 1][row0] = pb0.y;
        Bs[buf][c0 + 2][row0] = pb0.z;
        Bs[buf][c0 + 3][row0] = pb0.w;
        Bs[buf][c1 + 0][row1] = pb1.x;
        Bs[buf][c1 + 1][row1] = pb1.y;
        Bs[buf][c1 + 2][row1] = pb1.z;
        Bs[buf][c1 + 3][row1] = pb1.w;
        __syncthreads();

        // Kick off next tile's global loads (latency hides under compute)
        if (kt < 63) {
            int off = (kt + 1) * 16;
            pa0 = *(const float4*)(xa0 + off);
            pa1 = *(const float4*)(xa1 + off);
            pb0 = *(const float4*)(wb0 + off);
            pb1 = *(const float4*)(wb1 + off);
        }

#pragma unroll
        for (int k = 0; k < 16; k++) {
            float a[8], b[8];
            *(float4*)&a[0] = *(const float4*)&As[buf][k][ty * 4];
            *(float4*)&a[4] = *(const float4*)&As[buf][k][64 + ty * 4];
            *(float4*)&b[0] = *(const float4*)&Bs[buf][k][tx * 4];
            *(float4*)&b[4] = *(const float4*)&Bs[buf][k][64 + tx * 4];
#pragma unroll
            for (int i = 0; i < 8; i++)
#pragma unroll
                for (int j = 0; j < 8; j++)
                    acc[i][j] += a[i] * b[j];
        }
        buf ^= 1;
    }

    // Epilogue: add bias, scatter into q/k/v [B,H,N,D]
#pragma unroll
    for (int i = 0; i < 8; i++) {
        int m  = m0 + ((i < 4) ? (ty * 4 + i) : (64 + ty * 4 + i - 4));
        int bb = m >> 11;          // m / N
        int n  = m & (cN - 1);
#pragma unroll
        for (int j = 0; j < 8; j++) {
            int e = e0 + ((j < 4) ? (tx * 4 + j) : (64 + tx * 4 + j - 4));
            float v = acc[i][j] + __ldg(bias + e);
            int h   = e / 192;
            int rem = e - h * 192;
            int d   = rem / 3;
            int jj  = rem - d * 3;
            size_t idx = ((size_t)(bb * cH + h) * cN + n) * cD + d;
            if (jj == 0)      g_q[idx] = v;
            else if (jj == 1) g_k[idx] = v;
            else              g_v[idx] = v;
        }
    }
}

// ---------------------------------------------------------------------------
// Kernel 2: in-place RMS-norm over head dim for q (blockIdx.y=0) and k (=1).
// ---------------------------------------------------------------------------
__global__ __launch_bounds__(256) void rmsnorm(const float* __restrict__ qw,
                                               const float* __restrict__ kw) {
    int warp = threadIdx.x >> 5;
    int lane = threadIdx.x & 31;
    size_t row = (size_t)blockIdx.x * 8 + warp;     // < B*H*N = 65536
    float* base = blockIdx.y ? g_k : g_q;
    const float* wv = blockIdx.y ? kw : qw;

    float2 v = *(float2*)(base + row * cD + lane * 2);
    float ss = v.x * v.x + v.y * v.y;
#pragma unroll
    for (int o = 16; o > 0; o >>= 1) ss += __shfl_xor_sync(0xffffffffu, ss, o);
    float inv = rsqrtf(ss * (1.0f / cD) + 1e-6f);
    float2 g = *(const float2*)(wv + lane * 2);
    v.x *= inv * g.x;
    v.y *= inv * g.y;
    *(float2*)(base + row * cD + lane * 2) = v;
}

// ---------------------------------------------------------------------------
// Kernel 3: attention, flash-style WITHOUT online max (|score| <= 8 exactly,
// since RMS norm fixes ||q||=||k||=8 and scale=0.125).
// 128-row Q tile per CTA, 64-key tiles, 256 threads, 8x4 per thread.
// Smem (dynamic, 96KB): Qs[128][64], Ks[64][64] (transposed [d][c]),
// Vs[64][64], Ps[128][64]. 3 syncs per key-tile. 2 CTAs/SM.
// ---------------------------------------------------------------------------
__global__ __launch_bounds__(256) void attn(float* __restrict__ out) {
    extern __shared__ float sm[];
    float* Qs = sm;                 // [128][64]
    float* Ks = sm + 8192;          // [64][64]  (K transposed: [d][c])
    float* Vs = sm + 12288;         // [64][64]  ([c][d])
    float* Ps = sm + 16384;         // [128][64]

    const int tid = threadIdx.x;
    const int tx = tid & 15;
    const int ty = tid >> 4;
    const int bh = blockIdx.y;             // 0..31  (b*H + h)
    const int q0 = blockIdx.x * 128;
    const float* qb = g_q + (size_t)bh * cN * cD;
    const float* kb = g_k + (size_t)bh * cN * cD;
    const float* vb = g_v + (size_t)bh * cN * cD;

    // Load Q tile (coalesced, row-major): 8192 floats / 256 thr = 8 float4
#pragma unroll
    for (int p = 0; p < 8; p++) {
        int l  = tid + p * 256;
        int r  = l >> 4;
        int c4 = (l & 15) * 4;
        *(float4*)&Qs[r * 64 + c4] = *(const float4*)(qb + (size_t)(q0 + r) * cD + c4);
    }

    float o[8][4];
    float lsum[8];
#pragma unroll
    for (int i = 0; i < 8; i++) {
        lsum[i] = 0.f;
#pragma unroll
        for (int j = 0; j < 4; j++) o[i][j] = 0.f;
    }

    for (int kt = 0; kt < cN; kt += 64) {
        __syncthreads();   // prev-iter Ps/Vs readers done (covers Q load on iter 0)

        // Load K tile transposed: Ks[d][c] = k[kt+c][d]
#pragma unroll
        for (int p = 0; p < 4; p++) {
            int l  = tid + p * 256;
            int c  = l & 63;
            int d4 = (l >> 6) * 4;
            float4 t = *(const float4*)(kb + (size_t)(kt + c) * cD + d4);
            Ks[(d4 + 0) * 64 + c] = t.x;
            Ks[(d4 + 1) * 64 + c] = t.y;
            Ks[(d4 + 2) * 64 + c] = t.z;
            Ks[(d4 + 3) * 64 + c] = t.w;
        }
        // Load V tile row-major: Vs[c][d]
#pragma unroll
        for (int p = 0; p < 4; p++) {
            int l  = tid + p * 256;
            int r  = l >> 4;
            int c4 = (l & 15) * 4;
            *(float4*)&Vs[r * 64 + c4] = *(const float4*)(vb + (size_t)(kt + r) * cD + c4);
        }
        __syncthreads();

        // S = Q K^T  (8x4 per thread)
        float s[8][4];
#pragma unroll
        for (int i = 0; i < 8; i++)
#pragma unroll
            for (int j = 0; j < 4; j++) s[i][j] = 0.f;

#pragma unroll
        for (int d4 = 0; d4 < 64; d4 += 4) {
            float qf[8][4], kf[4][4];
#pragma unroll
            for (int i = 0; i < 8; i++) {
                float4 t = *(const float4*)&Qs[(ty * 8 + i) * 64 + d4];
                qf[i][0] = t.x; qf[i][1] = t.y; qf[i][2] = t.z; qf[i][3] = t.w;
            }
#pragma unroll
            for (int dd = 0; dd < 4; dd++) {
                float4 t = *(const float4*)&Ks[(d4 + dd) * 64 + tx * 4];
                kf[dd][0] = t.x; kf[dd][1] = t.y; kf[dd][2] = t.z; kf[dd][3] = t.w;
            }
#pragma unroll
            for (int i = 0; i < 8; i++)
#pragma unroll
                for (int j = 0; j < 4; j++)
#pragma unroll
                    for (int dd = 0; dd < 4; dd++)
                        s[i][j] += qf[i][dd] * kf[dd][j];
        }

        // P = exp(S * scale); row-sum partials; stage P in smem
#pragma unroll
        for (int i = 0; i < 8; i++) {
            float4 pv;
            pv.x = __expf(s[i][0] * 0.125f);
            pv.y = __expf(s[i][1] * 0.125f);
            pv.z = __expf(s[i][2] * 0.125f);
            pv.w = __expf(s[i][3] * 0.125f);
            lsum[i] += pv.x + pv.y + pv.z + pv.w;
            *(float4*)&Ps[(ty * 8 + i) * 64 + tx * 4] = pv;
        }
        __syncthreads();

        // O += P * V
#pragma unroll
        for (int c4 = 0; c4 < 64; c4 += 4) {
            float pf[8][4], vf[4][4];
#pragma unroll
            for (int i = 0; i < 8; i++) {
                float4 t = *(const float4*)&Ps[(ty * 8 + i) * 64 + c4];
                pf[i][0] = t.x; pf[i][1] = t.y; pf[i][2] = t.z; pf[i][3] = t.w;
            }
#pragma unroll
            for (int cc = 0; cc < 4; cc++) {
                float4 t = *(const float4*)&Vs[(c4 + cc) * 64 + tx * 4];
                vf[cc][0] = t.x; vf[cc][1] = t.y; vf[cc][2] = t.z; vf[cc][3] = t.w;
            }
#pragma unroll
            for (int i = 0; i < 8; i++)
#pragma unroll
                for (int j = 0; j < 4; j++)
#pragma unroll
                    for (int cc = 0; cc < 4; cc++)
                        o[i][j] += pf[i][cc] * vf[cc][j];
        }
    }

    // Reduce row sums across the 16 tx lanes (tx group is contiguous in warp)
#pragma unroll
    for (int i = 0; i < 8; i++) {
#pragma unroll
        for (int off = 1; off < 16; off <<= 1)
            lsum[i] += __shfl_xor_sync(0xffffffffu, lsum[i], off);
    }

    // Write out: out[b][n][h*64 + d]
    int bb = bh >> 4;
    int h  = bh & 15;
#pragma unroll
    for (int i = 0; i < 8; i++) {
        int n = q0 + ty * 8 + i;
        float inv = 1.0f / lsum[i];
        float4 r4;
        r4.x = o[i][0] * inv;
        r4.y = o[i][1] * inv;
        r4.z = o[i][2] * inv;
        r4.w = o[i][3] * inv;
        *(float4*)(out + ((size_t)(bb * cN + n)) * cDIM + h * cD + tx * 4) = r4;
    }
}

// ---------------------------------------------------------------------------
extern "C" void kernel_launch(void* const* d_in, const int* in_sizes, int n_in,
                              void* d_out, int out_size) {
    const float* x        = (const float*)d_in[0];
    const float* qkv_w    = (const float*)d_in[1];
    const float* qkv_b    = (const float*)d_in[2];
    const float* q_norm_w = (const float*)d_in[3];
    const float* k_norm_w = (const float*)d_in[4];
    float* out = (float*)d_out;

    // Idempotent, not a stream op (graph-capture safe); no static guard.
    cudaFuncSetAttribute(attn, cudaFuncAttributeMaxDynamicSharedMemorySize,
                         96 * 1024);

    dim3 g1(cE / 128, cM / 128);         // 24 x 32
    qkv_gemm<<<g1, 256>>>(x, qkv_w, qkv_b);

    dim3 g2((cB * cH * cN) / 8, 2);      // 8192 x 2
    rmsnorm<<<g2, 256>>>(q_norm_w, k_norm_w);

    dim3 g3(cN / 128, cB * cH);          // 16 x 32
    attn<<<g3, 256, 96 * 1024>>>(out);
}